// round 1
// baseline (speedup 1.0000x reference)
#include <cuda_runtime.h>
#include <math.h>

// Problem constants
#define B_SZ   4
#define L_SZ   1024
#define D_SZ   768
#define DI_SZ  1536
#define DI2_SZ 3072
#define N_ST   16
#define DTR_SZ 48
#define XDBL_W 80           // DTR + 2*N
#define M_ROWS 4096         // B*L

// Scratch (device globals; no allocation allowed)
__device__ float g_xn  [M_ROWS * D_SZ];
__device__ float g_xz  [M_ROWS * DI2_SZ];
__device__ float g_xc  [M_ROWS * DI_SZ];
__device__ float g_xdbl[M_ROWS * XDBL_W];
__device__ float g_delta[M_ROWS * DI_SZ];
__device__ float g_y   [M_ROWS * DI_SZ];

// ---------------------------------------------------------------------------
// LayerNorm: one block (256 thr) per row of 768
// ---------------------------------------------------------------------------
__global__ void ln_kernel(const float* __restrict__ x,
                          const float* __restrict__ gam,
                          const float* __restrict__ bet)
{
    int row = blockIdx.x;
    const float* xr = x + (size_t)row * D_SZ;
    float v[3];
    float s = 0.f, sq = 0.f;
#pragma unroll
    for (int i = 0; i < 3; i++) {
        v[i] = xr[threadIdx.x + i * 256];
        s += v[i];
        sq += v[i] * v[i];
    }
#pragma unroll
    for (int o = 16; o > 0; o >>= 1) {
        s  += __shfl_xor_sync(0xffffffffu, s, o);
        sq += __shfl_xor_sync(0xffffffffu, sq, o);
    }
    __shared__ float ss[8], ssq[8];
    int w = threadIdx.x >> 5, lane = threadIdx.x & 31;
    if (lane == 0) { ss[w] = s; ssq[w] = sq; }
    __syncthreads();
    if (w == 0) {
        s  = (lane < 8) ? ss[lane]  : 0.f;
        sq = (lane < 8) ? ssq[lane] : 0.f;
#pragma unroll
        for (int o = 4; o > 0; o >>= 1) {
            s  += __shfl_xor_sync(0xffffffffu, s, o);
            sq += __shfl_xor_sync(0xffffffffu, sq, o);
        }
        if (lane == 0) { ss[0] = s; ssq[0] = sq; }
    }
    __syncthreads();
    float mu  = ss[0] * (1.f / D_SZ);
    float var = ssq[0] * (1.f / D_SZ) - mu * mu;
    float rs  = rsqrtf(var + 1e-6f);
#pragma unroll
    for (int i = 0; i < 3; i++) {
        int c = threadIdx.x + i * 256;
        g_xn[(size_t)row * D_SZ + c] = (v[i] - mu) * rs * gam[c] + bet[c];
    }
}

// ---------------------------------------------------------------------------
// Generic NT GEMM: C[M,N] = sum_k A[m*lda+k] * B[n*ldb+k]  (+ epilogue)
// 128x128x8 tile, 256 threads, 8x8 per thread, register prefetch.
// EPI 0: plain   EPI 1: softplus(acc + bias[n])   EPI 2: relu(acc)+resid
// ---------------------------------------------------------------------------
template <int EPI>
__global__ __launch_bounds__(256)
void gemm_nt(const float* __restrict__ A, int lda,
             const float* __restrict__ Bm, int ldb,
             float* __restrict__ C, int M, int N, int K,
             const float* __restrict__ bias,
             const float* __restrict__ resid)
{
    __shared__ float As[8][132];
    __shared__ float Bs[8][132];

    int t  = threadIdx.x;
    int tx = t & 15, ty = t >> 4;
    int row0 = blockIdx.y * 128;
    int col0 = blockIdx.x * 128;

    int am = t >> 1;              // 0..127 tile row
    int ak = (t & 1) * 4;         // 0 or 4 (k quad)
    const float* Aptr = A + (size_t)(row0 + am) * lda + ak;
    int brow = col0 + am;
    bool bok = (brow < N);
    const float* Bptr = bok ? (Bm + (size_t)brow * ldb + ak) : Bm;

    float acc[8][8];
#pragma unroll
    for (int i = 0; i < 8; i++)
#pragma unroll
        for (int j = 0; j < 8; j++) acc[i][j] = 0.f;

    int nsteps = K / 8;
    float4 ra = *(const float4*)Aptr;
    float4 rb = bok ? *(const float4*)Bptr : make_float4(0.f, 0.f, 0.f, 0.f);

    for (int s = 0;;) {
        As[ak + 0][am] = ra.x; As[ak + 1][am] = ra.y;
        As[ak + 2][am] = ra.z; As[ak + 3][am] = ra.w;
        Bs[ak + 0][am] = rb.x; Bs[ak + 1][am] = rb.y;
        Bs[ak + 2][am] = rb.z; Bs[ak + 3][am] = rb.w;
        __syncthreads();
        s++;
        bool more = (s < nsteps);
        if (more) {
            ra = *(const float4*)(Aptr + s * 8);
            rb = bok ? *(const float4*)(Bptr + s * 8)
                     : make_float4(0.f, 0.f, 0.f, 0.f);
        }
#pragma unroll
        for (int k = 0; k < 8; k++) {
            float a[8], b[8];
            float4 a0 = *(const float4*)&As[k][ty * 8];
            float4 a1 = *(const float4*)&As[k][ty * 8 + 4];
            float4 b0 = *(const float4*)&Bs[k][tx * 8];
            float4 b1 = *(const float4*)&Bs[k][tx * 8 + 4];
            a[0]=a0.x; a[1]=a0.y; a[2]=a0.z; a[3]=a0.w;
            a[4]=a1.x; a[5]=a1.y; a[6]=a1.z; a[7]=a1.w;
            b[0]=b0.x; b[1]=b0.y; b[2]=b0.z; b[3]=b0.w;
            b[4]=b1.x; b[5]=b1.y; b[6]=b1.z; b[7]=b1.w;
#pragma unroll
            for (int i = 0; i < 8; i++)
#pragma unroll
                for (int j = 0; j < 8; j++)
                    acc[i][j] = fmaf(a[i], b[j], acc[i][j]);
        }
        if (!more) break;
        __syncthreads();
    }

#pragma unroll
    for (int i = 0; i < 8; i++) {
        int r = row0 + ty * 8 + i;
#pragma unroll
        for (int j = 0; j < 8; j++) {
            int c = col0 + tx * 8 + j;
            if (c < N) {
                float v = acc[i][j];
                if (EPI == 1) {
                    v += bias[c];
                    v = (v > 20.f) ? v : log1pf(__expf(v));
                } else if (EPI == 2) {
                    v = fmaxf(v, 0.f) + resid[(size_t)r * N + c];
                }
                C[(size_t)r * N + c] = v;
            }
        }
    }
}

// ---------------------------------------------------------------------------
// Causal depthwise conv (width 4) + bias + SiLU; input is xz[..., :DI]
// ---------------------------------------------------------------------------
__global__ void conv_silu_kernel(const float* __restrict__ Wc,
                                 const float* __restrict__ bc)
{
    int gid = blockIdx.x * blockDim.x + threadIdx.x;
    if (gid >= M_ROWS * DI_SZ) return;
    int d  = gid % DI_SZ;
    int bl = gid / DI_SZ;
    int l  = bl % L_SZ;
    float acc = bc[d];
#pragma unroll
    for (int j = 0; j < 4; j++) {
        int ll = l - 3 + j;
        if (ll >= 0)
            acc = fmaf(Wc[d * 4 + j], g_xz[(size_t)(bl - 3 + j) * DI2_SZ + d], acc);
    }
    g_xc[gid] = acc / (1.f + __expf(-acc));
}

// ---------------------------------------------------------------------------
// Selective scan + skip + gate. 16 lanes per (b,d) chain, 2 chains per warp.
// y[b,l,d] = (sum_n h[n]*C[n] + u*Dp) * silu(z)
// ---------------------------------------------------------------------------
__global__ __launch_bounds__(256)
void scan_kernel(const float* __restrict__ A_log,
                 const float* __restrict__ Dpar)
{
    int gtid  = blockIdx.x * 256 + threadIdx.x;
    int chain = gtid >> 4;          // 0..6143
    int n     = gtid & 15;
    int b     = chain / DI_SZ;
    int d     = chain % DI_SZ;

    float a  = -__expf(A_log[d * N_ST + n]);
    float dp = Dpar[d];
    float h  = 0.f;
    int base = b * L_SZ;

    for (int l = 0; l < L_SZ; l++) {
        int bl = base + l;
        size_t ofs = (size_t)bl * DI_SZ + d;
        float delta = g_delta[ofs];
        float u     = g_xc[ofs];
        float Bv    = g_xdbl[bl * XDBL_W + DTR_SZ + n];
        float Cv    = g_xdbl[bl * XDBL_W + DTR_SZ + N_ST + n];
        float dA    = __expf(delta * a);
        h = fmaf(dA, h, delta * Bv * u);
        float s = h * Cv;
        s += __shfl_xor_sync(0xffffffffu, s, 8);
        s += __shfl_xor_sync(0xffffffffu, s, 4);
        s += __shfl_xor_sync(0xffffffffu, s, 2);
        s += __shfl_xor_sync(0xffffffffu, s, 1);
        if (n == 0) {
            float z   = g_xz[(size_t)bl * DI2_SZ + DI_SZ + d];
            float sil = z / (1.f + __expf(-z));
            g_y[ofs]  = (s + u * dp) * sil;
        }
    }
}

// ---------------------------------------------------------------------------
extern "C" void kernel_launch(void* const* d_in, const int* in_sizes, int n_in,
                              void* d_out, int out_size)
{
    const float* input   = (const float*)d_in[0];
    const float* ln_g    = (const float*)d_in[1];
    const float* ln_b    = (const float*)d_in[2];
    const float* W_in    = (const float*)d_in[3];
    const float* W_conv  = (const float*)d_in[4];
    const float* b_conv  = (const float*)d_in[5];
    const float* W_x     = (const float*)d_in[6];
    const float* W_dt    = (const float*)d_in[7];
    const float* b_dt    = (const float*)d_in[8];
    const float* A_log   = (const float*)d_in[9];
    const float* D_param = (const float*)d_in[10];
    const float* W_out   = (const float*)d_in[11];
    float* out = (float*)d_out;

    float *xn, *xz, *xc, *xdbl, *delta, *y;
    cudaGetSymbolAddress((void**)&xn,    g_xn);
    cudaGetSymbolAddress((void**)&xz,    g_xz);
    cudaGetSymbolAddress((void**)&xc,    g_xc);
    cudaGetSymbolAddress((void**)&xdbl,  g_xdbl);
    cudaGetSymbolAddress((void**)&delta, g_delta);
    cudaGetSymbolAddress((void**)&y,     g_y);

    // 1. LayerNorm
    ln_kernel<<<M_ROWS, 256>>>(input, ln_g, ln_b);

    // 2. in-proj: xz = xn @ W_in^T   (4096 x 3072 x 768)
    {
        dim3 g(DI2_SZ / 128, M_ROWS / 128);
        gemm_nt<0><<<g, 256>>>(xn, D_SZ, W_in, D_SZ, xz,
                               M_ROWS, DI2_SZ, D_SZ, nullptr, nullptr);
    }

    // 3. causal depthwise conv + SiLU -> xc
    {
        int total = M_ROWS * DI_SZ;
        conv_silu_kernel<<<(total + 255) / 256, 256>>>(W_conv, b_conv);
    }

    // 4. x_dbl = xc @ W_x^T   (4096 x 80 x 1536)
    {
        dim3 g(1, M_ROWS / 128);
        gemm_nt<0><<<g, 256>>>(xc, DI_SZ, W_x, DI_SZ, xdbl,
                               M_ROWS, XDBL_W, DI_SZ, nullptr, nullptr);
    }

    // 5. delta = softplus(dt @ W_dt^T + b_dt)   (4096 x 1536 x 48)
    {
        dim3 g(DI_SZ / 128, M_ROWS / 128);
        gemm_nt<1><<<g, 256>>>(xdbl, XDBL_W, W_dt, DTR_SZ, delta,
                               M_ROWS, DI_SZ, DTR_SZ, b_dt, nullptr);
    }

    // 6. selective scan + skip + gating -> y
    {
        int threads = B_SZ * DI_SZ * N_ST;   // 98304
        scan_kernel<<<threads / 256, 256>>>(A_log, D_param);
    }

    // 7. out = relu(y @ W_out^T) + input   (4096 x 768 x 1536)
    {
        dim3 g(D_SZ / 128, M_ROWS / 128);
        gemm_nt<2><<<g, 256>>>(y, DI_SZ, W_out, DI_SZ, out,
                               M_ROWS, D_SZ, DI_SZ, nullptr, input);
    }
}

// round 3
// speedup vs baseline: 1.1772x; 1.1772x over previous
#include <cuda_runtime.h>
#include <math.h>
#include <stdint.h>

// Problem constants
#define B_SZ   4
#define L_SZ   1024
#define D_SZ   768
#define DI_SZ  1536
#define DI2_SZ 3072
#define N_ST   16
#define DTR_SZ 48
#define XDBL_W 80           // DTR + 2*N
#define M_ROWS 4096         // B*L

// Scratch (device globals; no allocation allowed)
__device__ float g_xn  [M_ROWS * D_SZ];
__device__ float g_xz  [M_ROWS * DI2_SZ];
__device__ float g_xc  [M_ROWS * DI_SZ];
__device__ float g_xdbl[M_ROWS * XDBL_W];
__device__ float g_delta[M_ROWS * DI_SZ];
__device__ float g_y   [M_ROWS * DI_SZ];

__device__ __forceinline__ float f2tf32(float x) {
    uint32_t u;
    asm("cvt.rna.tf32.f32 %0, %1;" : "=r"(u) : "f"(x));
    return __uint_as_float(u);
}

__device__ __forceinline__ void mma8(float& d0, float& d1, float& d2, float& d3,
                                     uint32_t a0, uint32_t a1, uint32_t a2, uint32_t a3,
                                     uint32_t b0, uint32_t b1) {
    asm volatile(
        "mma.sync.aligned.m16n8k8.row.col.f32.tf32.tf32.f32 "
        "{%0,%1,%2,%3}, {%4,%5,%6,%7}, {%8,%9}, {%0,%1,%2,%3};"
        : "+f"(d0), "+f"(d1), "+f"(d2), "+f"(d3)
        : "r"(a0), "r"(a1), "r"(a2), "r"(a3), "r"(b0), "r"(b1));
}

// ---------------------------------------------------------------------------
// LayerNorm: one block (256 thr) per row of 768
// ---------------------------------------------------------------------------
__global__ void ln_kernel(const float* __restrict__ x,
                          const float* __restrict__ gam,
                          const float* __restrict__ bet)
{
    int row = blockIdx.x;
    const float* xr = x + (size_t)row * D_SZ;
    float v[3];
    float s = 0.f, sq = 0.f;
#pragma unroll
    for (int i = 0; i < 3; i++) {
        v[i] = xr[threadIdx.x + i * 256];
        s += v[i];
        sq += v[i] * v[i];
    }
#pragma unroll
    for (int o = 16; o > 0; o >>= 1) {
        s  += __shfl_xor_sync(0xffffffffu, s, o);
        sq += __shfl_xor_sync(0xffffffffu, sq, o);
    }
    __shared__ float ss[8], ssq[8];
    int w = threadIdx.x >> 5, lane = threadIdx.x & 31;
    if (lane == 0) { ss[w] = s; ssq[w] = sq; }
    __syncthreads();
    if (w == 0) {
        s  = (lane < 8) ? ss[lane]  : 0.f;
        sq = (lane < 8) ? ssq[lane] : 0.f;
#pragma unroll
        for (int o = 4; o > 0; o >>= 1) {
            s  += __shfl_xor_sync(0xffffffffu, s, o);
            sq += __shfl_xor_sync(0xffffffffu, sq, o);
        }
        if (lane == 0) { ss[0] = s; ssq[0] = sq; }
    }
    __syncthreads();
    float mu  = ss[0] * (1.f / D_SZ);
    float var = ssq[0] * (1.f / D_SZ) - mu * mu;
    float rs  = rsqrtf(var + 1e-6f);
#pragma unroll
    for (int i = 0; i < 3; i++) {
        int c = threadIdx.x + i * 256;
        g_xn[(size_t)row * D_SZ + c] = (v[i] - mu) * rs * gam[c] + bet[c];
    }
}

// ---------------------------------------------------------------------------
// Tensor-core TF32 NT GEMM (mma.sync m16n8k8) with 3xTF32 accuracy.
//   C[M,N] = sum_k A[m*lda+k] * B[n*ldb+k]  (+ epilogue)
// Tile 128x128x16, 256 threads (8 warps, 2x4), warp tile 64x32.
// EPI 0: plain   EPI 1: softplus(acc + bias[n])   EPI 2: relu(acc)+resid
// ---------------------------------------------------------------------------
#define BKC 16
#define SST 20     // smem row stride (16 + 4 pad) -> conflict-free frag LDS

template <int EPI>
__global__ __launch_bounds__(256)
void mgemm(const float* __restrict__ A, int lda,
           const float* __restrict__ Bm, int ldb,
           float* __restrict__ C, int M, int N, int K,
           const float* __restrict__ bias,
           const float* __restrict__ resid)
{
    __shared__ __align__(16) float As[2][128 * SST];
    __shared__ __align__(16) float Bs[2][128 * SST];

    int tid = threadIdx.x;
    int wid = tid >> 5, lane = tid & 31;
    int wm = (wid & 1) * 64;        // warp row offset
    int wn = (wid >> 1) * 32;       // warp col offset
    int grp = lane >> 2, qd = lane & 3;
    int row0 = blockIdx.y * 128, col0 = blockIdx.x * 128;

    float acc[4][4][4];
#pragma unroll
    for (int mi = 0; mi < 4; mi++)
#pragma unroll
        for (int ni = 0; ni < 4; ni++)
#pragma unroll
            for (int e = 0; e < 4; e++) acc[mi][ni][e] = 0.f;

    int lrow = tid >> 2;            // 0..63
    int lc4  = (tid & 3) * 4;       // 0,4,8,12

    const int nch = K / BKC;
    float4 pa[2], pb[2];

    // prefetch chunk 0
#pragma unroll
    for (int i = 0; i < 2; i++) {
        int r = lrow + 64 * i;
        pa[i] = *(const float4*)(A + (size_t)(row0 + r) * lda + lc4);
        int n = col0 + r;
        pb[i] = (n < N) ? *(const float4*)(Bm + (size_t)n * ldb + lc4)
                        : make_float4(0.f, 0.f, 0.f, 0.f);
    }
    // store chunk 0
#pragma unroll
    for (int i = 0; i < 2; i++) {
        int r = lrow + 64 * i;
        *(float4*)&As[0][r * SST + lc4] = pa[i];
        *(float4*)&Bs[0][r * SST + lc4] = pb[i];
    }
    __syncthreads();

    for (int c = 0; c < nch; c++) {
        int s = c & 1;
        // prefetch next chunk into registers
        if (c + 1 < nch) {
            int kc = (c + 1) * BKC;
#pragma unroll
            for (int i = 0; i < 2; i++) {
                int r = lrow + 64 * i;
                pa[i] = *(const float4*)(A + (size_t)(row0 + r) * lda + kc + lc4);
                int n = col0 + r;
                pb[i] = (n < N) ? *(const float4*)(Bm + (size_t)n * ldb + kc + lc4)
                                : make_float4(0.f, 0.f, 0.f, 0.f);
            }
        }

        // compute on stage s: 2 k-steps of 8
#pragma unroll
        for (int ks = 0; ks < 2; ks++) {
            int kb = ks * 8 + qd;
            uint32_t ahi[4][4], alo[4][4];
#pragma unroll
            for (int mi = 0; mi < 4; mi++) {
                int r = wm + mi * 16 + grp;
                float v0 = As[s][r * SST + kb];
                float v1 = As[s][(r + 8) * SST + kb];
                float v2 = As[s][r * SST + kb + 4];
                float v3 = As[s][(r + 8) * SST + kb + 4];
                float h0 = f2tf32(v0), h1 = f2tf32(v1);
                float h2 = f2tf32(v2), h3 = f2tf32(v3);
                ahi[mi][0] = __float_as_uint(h0);
                ahi[mi][1] = __float_as_uint(h1);
                ahi[mi][2] = __float_as_uint(h2);
                ahi[mi][3] = __float_as_uint(h3);
                alo[mi][0] = __float_as_uint(f2tf32(v0 - h0));
                alo[mi][1] = __float_as_uint(f2tf32(v1 - h1));
                alo[mi][2] = __float_as_uint(f2tf32(v2 - h2));
                alo[mi][3] = __float_as_uint(f2tf32(v3 - h3));
            }
            uint32_t bhi[4][2], blo[4][2];
#pragma unroll
            for (int ni = 0; ni < 4; ni++) {
                int n = wn + ni * 8 + grp;
                float v0 = Bs[s][n * SST + kb];
                float v1 = Bs[s][n * SST + ((ks * 8 + ((qd + 4) & 7)))];
                // note: b1 k-row = qd+4 (qd in 0..3 so qd+4 in 4..7)
                v1 = Bs[s][n * SST + ks * 8 + qd + 4];
                float h0 = f2tf32(v0), h1 = f2tf32(v1);
                bhi[ni][0] = __float_as_uint(h0);
                bhi[ni][1] = __float_as_uint(h1);
                blo[ni][0] = __float_as_uint(f2tf32(v0 - h0));
                blo[ni][1] = __float_as_uint(f2tf32(v1 - h1));
            }
#pragma unroll
            for (int mi = 0; mi < 4; mi++)
#pragma unroll
                for (int ni = 0; ni < 4; ni++) {
                    float* d = acc[mi][ni];
                    mma8(d[0], d[1], d[2], d[3],
                         ahi[mi][0], ahi[mi][1], ahi[mi][2], ahi[mi][3],
                         bhi[ni][0], bhi[ni][1]);
                    mma8(d[0], d[1], d[2], d[3],
                         ahi[mi][0], ahi[mi][1], ahi[mi][2], ahi[mi][3],
                         blo[ni][0], blo[ni][1]);
                    mma8(d[0], d[1], d[2], d[3],
                         alo[mi][0], alo[mi][1], alo[mi][2], alo[mi][3],
                         bhi[ni][0], bhi[ni][1]);
                }
        }

        // store next chunk
        if (c + 1 < nch) {
            int s2 = (c + 1) & 1;
#pragma unroll
            for (int i = 0; i < 2; i++) {
                int r = lrow + 64 * i;
                *(float4*)&As[s2][r * SST + lc4] = pa[i];
                *(float4*)&Bs[s2][r * SST + lc4] = pb[i];
            }
            __syncthreads();
        }
    }

    // epilogue: write from registers (c0,c1 contiguous pair; c2,c3 at row+8)
#pragma unroll
    for (int mi = 0; mi < 4; mi++) {
#pragma unroll
        for (int ni = 0; ni < 4; ni++) {
            int r  = row0 + wm + mi * 16 + grp;
            int cc = col0 + wn + ni * 8 + qd * 2;
            if (cc < N) {
#pragma unroll
                for (int h = 0; h < 2; h++) {
                    int rr = r + h * 8;
                    float v0 = acc[mi][ni][h * 2 + 0];
                    float v1 = acc[mi][ni][h * 2 + 1];
                    if (EPI == 1) {
                        v0 += bias[cc];
                        v1 += bias[cc + 1];
                        v0 = (v0 > 20.f) ? v0 : log1pf(__expf(v0));
                        v1 = (v1 > 20.f) ? v1 : log1pf(__expf(v1));
                    } else if (EPI == 2) {
                        v0 = fmaxf(v0, 0.f) + resid[(size_t)rr * N + cc];
                        v1 = fmaxf(v1, 0.f) + resid[(size_t)rr * N + cc + 1];
                    }
                    float2 o; o.x = v0; o.y = v1;
                    *(float2*)(C + (size_t)rr * N + cc) = o;
                }
            }
        }
    }
}

// ---------------------------------------------------------------------------
// Causal depthwise conv (width 4) + bias + SiLU; input is xz[..., :DI]
// ---------------------------------------------------------------------------
__global__ void conv_silu_kernel(const float* __restrict__ Wc,
                                 const float* __restrict__ bc)
{
    int gid = blockIdx.x * blockDim.x + threadIdx.x;
    if (gid >= M_ROWS * DI_SZ) return;
    int d  = gid % DI_SZ;
    int bl = gid / DI_SZ;
    int l  = bl % L_SZ;
    float acc = bc[d];
#pragma unroll
    for (int j = 0; j < 4; j++) {
        int ll = l - 3 + j;
        if (ll >= 0)
            acc = fmaf(Wc[d * 4 + j], g_xz[(size_t)(bl - 3 + j) * DI2_SZ + d], acc);
    }
    g_xc[gid] = acc / (1.f + __expf(-acc));
}

// ---------------------------------------------------------------------------
// Selective scan + skip + gate. 16 lanes per (b,d) chain, 2 chains per warp.
// ---------------------------------------------------------------------------
__global__ __launch_bounds__(256)
void scan_kernel(const float* __restrict__ A_log,
                 const float* __restrict__ Dpar)
{
    int gtid  = blockIdx.x * 256 + threadIdx.x;
    int chain = gtid >> 4;          // 0..6143
    int n     = gtid & 15;
    int b     = chain / DI_SZ;
    int d     = chain % DI_SZ;

    float a  = -__expf(A_log[d * N_ST + n]);
    float dp = Dpar[d];
    float h  = 0.f;
    int base = b * L_SZ;

    for (int l = 0; l < L_SZ; l++) {
        int bl = base + l;
        size_t ofs = (size_t)bl * DI_SZ + d;
        float delta = g_delta[ofs];
        float u     = g_xc[ofs];
        float Bv    = g_xdbl[bl * XDBL_W + DTR_SZ + n];
        float Cv    = g_xdbl[bl * XDBL_W + DTR_SZ + N_ST + n];
        float dA    = __expf(delta * a);
        h = fmaf(dA, h, delta * Bv * u);
        float s = h * Cv;
        s += __shfl_xor_sync(0xffffffffu, s, 8);
        s += __shfl_xor_sync(0xffffffffu, s, 4);
        s += __shfl_xor_sync(0xffffffffu, s, 2);
        s += __shfl_xor_sync(0xffffffffu, s, 1);
        if (n == 0) {
            float z   = g_xz[(size_t)bl * DI2_SZ + DI_SZ + d];
            float sil = z / (1.f + __expf(-z));
            g_y[ofs]  = (s + u * dp) * sil;
        }
    }
}

// ---------------------------------------------------------------------------
extern "C" void kernel_launch(void* const* d_in, const int* in_sizes, int n_in,
                              void* d_out, int out_size)
{
    const float* input   = (const float*)d_in[0];
    const float* ln_g    = (const float*)d_in[1];
    const float* ln_b    = (const float*)d_in[2];
    const float* W_in    = (const float*)d_in[3];
    const float* W_conv  = (const float*)d_in[4];
    const float* b_conv  = (const float*)d_in[5];
    const float* W_x     = (const float*)d_in[6];
    const float* W_dt    = (const float*)d_in[7];
    const float* b_dt    = (const float*)d_in[8];
    const float* A_log   = (const float*)d_in[9];
    const float* D_param = (const float*)d_in[10];
    const float* W_out   = (const float*)d_in[11];
    float* out = (float*)d_out;

    float *xn, *xz, *xc, *xdbl, *delta, *y;
    cudaGetSymbolAddress((void**)&xn,    g_xn);
    cudaGetSymbolAddress((void**)&xz,    g_xz);
    cudaGetSymbolAddress((void**)&xc,    g_xc);
    cudaGetSymbolAddress((void**)&xdbl,  g_xdbl);
    cudaGetSymbolAddress((void**)&delta, g_delta);
    cudaGetSymbolAddress((void**)&y,     g_y);

    // 1. LayerNorm
    ln_kernel<<<M_ROWS, 256>>>(input, ln_g, ln_b);

    // 2. in-proj: xz = xn @ W_in^T   (4096 x 3072 x 768)
    {
        dim3 g(DI2_SZ / 128, M_ROWS / 128);
        mgemm<0><<<g, 256>>>(xn, D_SZ, W_in, D_SZ, xz,
                             M_ROWS, DI2_SZ, D_SZ, nullptr, nullptr);
    }

    // 3. causal depthwise conv + SiLU -> xc
    {
        int total = M_ROWS * DI_SZ;
        conv_silu_kernel<<<(total + 255) / 256, 256>>>(W_conv, b_conv);
    }

    // 4. x_dbl = xc @ W_x^T   (4096 x 80 x 1536)
    {
        dim3 g(1, M_ROWS / 128);
        mgemm<0><<<g, 256>>>(xc, DI_SZ, W_x, DI_SZ, xdbl,
                             M_ROWS, XDBL_W, DI_SZ, nullptr, nullptr);
    }

    // 5. delta = softplus(dt @ W_dt^T + b_dt)   (4096 x 1536 x 48)
    {
        dim3 g(DI_SZ / 128, M_ROWS / 128);
        mgemm<1><<<g, 256>>>(xdbl, XDBL_W, W_dt, DTR_SZ, delta,
                             M_ROWS, DI_SZ, DTR_SZ, b_dt, nullptr);
    }

    // 6. selective scan + skip + gating -> y
    {
        int threads = B_SZ * DI_SZ * N_ST;   // 98304
        scan_kernel<<<threads / 256, 256>>>(A_log, D_param);
    }

    // 7. out = relu(y @ W_out^T) + input   (4096 x 768 x 1536)
    {
        dim3 g(D_SZ / 128, M_ROWS / 128);
        mgemm<2><<<g, 256>>>(y, DI_SZ, W_out, DI_SZ, out,
                             M_ROWS, D_SZ, DI_SZ, nullptr, input);
    }
}

// round 4
// speedup vs baseline: 1.2654x; 1.0749x over previous
#include <cuda_runtime.h>
#include <math.h>
#include <stdint.h>

// Problem constants
#define B_SZ   4
#define L_SZ   1024
#define D_SZ   768
#define DI_SZ  1536
#define DI2_SZ 3072
#define N_ST   16
#define DTR_SZ 48
#define XDBL_W 80           // DTR + 2*N
#define M_ROWS 4096         // B*L
#define KSPLIT 4
#define XPART  (M_ROWS * XDBL_W)

// Scratch (device globals; no allocation allowed)
__device__ float g_xn  [M_ROWS * D_SZ];
__device__ float g_xz  [M_ROWS * DI2_SZ];
__device__ float g_xc  [M_ROWS * DI_SZ];
__device__ float g_xdbl[M_ROWS * XDBL_W];
__device__ float g_xpart[KSPLIT * XPART];
__device__ float g_delta[M_ROWS * DI_SZ];
__device__ float g_y   [M_ROWS * DI_SZ];

__device__ __forceinline__ float f2tf32(float x) {
    uint32_t u;
    asm("cvt.rna.tf32.f32 %0, %1;" : "=r"(u) : "f"(x));
    return __uint_as_float(u);
}

__device__ __forceinline__ void mma8(float* d,
                                     const uint32_t* a, const uint32_t* b) {
    asm volatile(
        "mma.sync.aligned.m16n8k8.row.col.f32.tf32.tf32.f32 "
        "{%0,%1,%2,%3}, {%4,%5,%6,%7}, {%8,%9}, {%0,%1,%2,%3};"
        : "+f"(d[0]), "+f"(d[1]), "+f"(d[2]), "+f"(d[3])
        : "r"(a[0]), "r"(a[1]), "r"(a[2]), "r"(a[3]), "r"(b[0]), "r"(b[1]));
}

// ---------------------------------------------------------------------------
// LayerNorm: one block (256 thr) per row of 768
// ---------------------------------------------------------------------------
__global__ void ln_kernel(const float* __restrict__ x,
                          const float* __restrict__ gam,
                          const float* __restrict__ bet)
{
    int row = blockIdx.x;
    const float* xr = x + (size_t)row * D_SZ;
    float v[3];
    float s = 0.f, sq = 0.f;
#pragma unroll
    for (int i = 0; i < 3; i++) {
        v[i] = xr[threadIdx.x + i * 256];
        s += v[i];
        sq += v[i] * v[i];
    }
#pragma unroll
    for (int o = 16; o > 0; o >>= 1) {
        s  += __shfl_xor_sync(0xffffffffu, s, o);
        sq += __shfl_xor_sync(0xffffffffu, sq, o);
    }
    __shared__ float ss[8], ssq[8];
    int w = threadIdx.x >> 5, lane = threadIdx.x & 31;
    if (lane == 0) { ss[w] = s; ssq[w] = sq; }
    __syncthreads();
    if (w == 0) {
        s  = (lane < 8) ? ss[lane]  : 0.f;
        sq = (lane < 8) ? ssq[lane] : 0.f;
#pragma unroll
        for (int o = 4; o > 0; o >>= 1) {
            s  += __shfl_xor_sync(0xffffffffu, s, o);
            sq += __shfl_xor_sync(0xffffffffu, sq, o);
        }
        if (lane == 0) { ss[0] = s; ssq[0] = sq; }
    }
    __syncthreads();
    float mu  = ss[0] * (1.f / D_SZ);
    float var = ssq[0] * (1.f / D_SZ) - mu * mu;
    float rs  = rsqrtf(var + 1e-6f);
#pragma unroll
    for (int i = 0; i < 3; i++) {
        int c = threadIdx.x + i * 256;
        g_xn[(size_t)row * D_SZ + c] = (v[i] - mu) * rs * gam[c] + bet[c];
    }
}

// ---------------------------------------------------------------------------
// Tensor-core TF32 NT GEMM (mma.sync m16n8k8), 3xTF32 accuracy.
// Pre-split hi/lo in SMEM; pass-ordered independent MMA batches.
// Tile 128x128x16, 256 threads (8 warps 2x4), warp tile 64x32.
// gridDim.z = split-K factor (A k-offset z*K, C offset z*zC).
// EPI 0: plain   EPI 1: softplus(acc + bias[n])   EPI 2: relu(acc)+resid
// ---------------------------------------------------------------------------
#define SST    20                 // smem row stride (16 + 4 pad)
#define TILE_F (128 * SST)        // floats per tile per stage
#define GSMEM  (8 * TILE_F * 4)   // 81920 bytes

template <int EPI>
__global__ __launch_bounds__(256)
void mgemm(const float* __restrict__ A, int lda,
           const float* __restrict__ Bm, int ldb,
           float* __restrict__ C, int M, int N, int K,
           const float* __restrict__ bias,
           const float* __restrict__ resid, size_t zC)
{
    extern __shared__ float sm[];
    // layout: Ahi[s]=s*T  Alo[s]=(2+s)*T  Bhi[s]=(4+s)*T  Blo[s]=(6+s)*T

    A += (size_t)blockIdx.z * K;       // split-K slice
    C += (size_t)blockIdx.z * zC;

    int tid = threadIdx.x;
    int wid = tid >> 5, lane = tid & 31;
    int wm = (wid & 1) * 64;
    int wn = (wid >> 1) * 32;
    int grp = lane >> 2, qd = lane & 3;
    int row0 = blockIdx.y * 128, col0 = blockIdx.x * 128;

    float acc[4][4][4];
#pragma unroll
    for (int mi = 0; mi < 4; mi++)
#pragma unroll
        for (int ni = 0; ni < 4; ni++)
#pragma unroll
            for (int e = 0; e < 4; e++) acc[mi][ni][e] = 0.f;

    int lrow = tid >> 2;            // 0..63
    int lc4  = (tid & 3) * 4;       // 0,4,8,12

    const int nch = K / 16;
    float4 pa[2], pb[2];

#pragma unroll
    for (int i = 0; i < 2; i++) {
        int r = lrow + 64 * i;
        pa[i] = *(const float4*)(A + (size_t)(row0 + r) * lda + lc4);
        int n = col0 + r;
        pb[i] = (n < N) ? *(const float4*)(Bm + (size_t)n * ldb + lc4)
                        : make_float4(0.f, 0.f, 0.f, 0.f);
    }
    // split + store chunk 0 into stage 0
#pragma unroll
    for (int i = 0; i < 2; i++) {
        int r = lrow + 64 * i;
        float4 h, l;
        h.x = f2tf32(pa[i].x); l.x = f2tf32(pa[i].x - h.x);
        h.y = f2tf32(pa[i].y); l.y = f2tf32(pa[i].y - h.y);
        h.z = f2tf32(pa[i].z); l.z = f2tf32(pa[i].z - h.z);
        h.w = f2tf32(pa[i].w); l.w = f2tf32(pa[i].w - h.w);
        *(float4*)&sm[0 * TILE_F + r * SST + lc4] = h;
        *(float4*)&sm[2 * TILE_F + r * SST + lc4] = l;
        h.x = f2tf32(pb[i].x); l.x = f2tf32(pb[i].x - h.x);
        h.y = f2tf32(pb[i].y); l.y = f2tf32(pb[i].y - h.y);
        h.z = f2tf32(pb[i].z); l.z = f2tf32(pb[i].z - h.z);
        h.w = f2tf32(pb[i].w); l.w = f2tf32(pb[i].w - h.w);
        *(float4*)&sm[4 * TILE_F + r * SST + lc4] = h;
        *(float4*)&sm[6 * TILE_F + r * SST + lc4] = l;
    }
    __syncthreads();

    for (int c = 0; c < nch; c++) {
        int s = c & 1;
        if (c + 1 < nch) {
            int kc = (c + 1) * 16;
#pragma unroll
            for (int i = 0; i < 2; i++) {
                int r = lrow + 64 * i;
                pa[i] = *(const float4*)(A + (size_t)(row0 + r) * lda + kc + lc4);
                int n = col0 + r;
                pb[i] = (n < N) ? *(const float4*)(Bm + (size_t)n * ldb + kc + lc4)
                                : make_float4(0.f, 0.f, 0.f, 0.f);
            }
        }

        const float* shAhi = sm + s * TILE_F;
        const float* shAlo = sm + (2 + s) * TILE_F;
        const float* shBhi = sm + (4 + s) * TILE_F;
        const float* shBlo = sm + (6 + s) * TILE_F;

#pragma unroll
        for (int ks = 0; ks < 2; ks++) {
            int kb = ks * 8 + qd;
            uint32_t ahi[4][4], bhi[4][2];
#pragma unroll
            for (int mi = 0; mi < 4; mi++) {
                int r = wm + mi * 16 + grp;
                ahi[mi][0] = __float_as_uint(shAhi[r * SST + kb]);
                ahi[mi][1] = __float_as_uint(shAhi[(r + 8) * SST + kb]);
                ahi[mi][2] = __float_as_uint(shAhi[r * SST + kb + 4]);
                ahi[mi][3] = __float_as_uint(shAhi[(r + 8) * SST + kb + 4]);
            }
#pragma unroll
            for (int ni = 0; ni < 4; ni++) {
                int n = wn + ni * 8 + grp;
                bhi[ni][0] = __float_as_uint(shBhi[n * SST + kb]);
                bhi[ni][1] = __float_as_uint(shBhi[n * SST + kb + 4]);
            }
            // pass 1: hi*hi — 16 independent MMAs
#pragma unroll
            for (int mi = 0; mi < 4; mi++)
#pragma unroll
                for (int ni = 0; ni < 4; ni++)
                    mma8(acc[mi][ni], ahi[mi], bhi[ni]);
            // pass 2: lo*hi
            {
                uint32_t alo[4][4];
#pragma unroll
                for (int mi = 0; mi < 4; mi++) {
                    int r = wm + mi * 16 + grp;
                    alo[mi][0] = __float_as_uint(shAlo[r * SST + kb]);
                    alo[mi][1] = __float_as_uint(shAlo[(r + 8) * SST + kb]);
                    alo[mi][2] = __float_as_uint(shAlo[r * SST + kb + 4]);
                    alo[mi][3] = __float_as_uint(shAlo[(r + 8) * SST + kb + 4]);
                }
#pragma unroll
                for (int mi = 0; mi < 4; mi++)
#pragma unroll
                    for (int ni = 0; ni < 4; ni++)
                        mma8(acc[mi][ni], alo[mi], bhi[ni]);
            }
            // pass 3: hi*lo
            {
                uint32_t blo[4][2];
#pragma unroll
                for (int ni = 0; ni < 4; ni++) {
                    int n = wn + ni * 8 + grp;
                    blo[ni][0] = __float_as_uint(shBlo[n * SST + kb]);
                    blo[ni][1] = __float_as_uint(shBlo[n * SST + kb + 4]);
                }
#pragma unroll
                for (int mi = 0; mi < 4; mi++)
#pragma unroll
                    for (int ni = 0; ni < 4; ni++)
                        mma8(acc[mi][ni], ahi[mi], blo[ni]);
            }
        }

        if (c + 1 < nch) {
            int s2 = (c + 1) & 1;
#pragma unroll
            for (int i = 0; i < 2; i++) {
                int r = lrow + 64 * i;
                float4 h, l;
                h.x = f2tf32(pa[i].x); l.x = f2tf32(pa[i].x - h.x);
                h.y = f2tf32(pa[i].y); l.y = f2tf32(pa[i].y - h.y);
                h.z = f2tf32(pa[i].z); l.z = f2tf32(pa[i].z - h.z);
                h.w = f2tf32(pa[i].w); l.w = f2tf32(pa[i].w - h.w);
                *(float4*)&sm[s2 * TILE_F + r * SST + lc4] = h;
                *(float4*)&sm[(2 + s2) * TILE_F + r * SST + lc4] = l;
                h.x = f2tf32(pb[i].x); l.x = f2tf32(pb[i].x - h.x);
                h.y = f2tf32(pb[i].y); l.y = f2tf32(pb[i].y - h.y);
                h.z = f2tf32(pb[i].z); l.z = f2tf32(pb[i].z - h.z);
                h.w = f2tf32(pb[i].w); l.w = f2tf32(pb[i].w - h.w);
                *(float4*)&sm[(4 + s2) * TILE_F + r * SST + lc4] = h;
                *(float4*)&sm[(6 + s2) * TILE_F + r * SST + lc4] = l;
            }
            __syncthreads();
        }
    }

    // epilogue: registers -> gmem
#pragma unroll
    for (int mi = 0; mi < 4; mi++) {
#pragma unroll
        for (int ni = 0; ni < 4; ni++) {
            int r  = row0 + wm + mi * 16 + grp;
            int cc = col0 + wn + ni * 8 + qd * 2;
            if (cc < N) {
#pragma unroll
                for (int h = 0; h < 2; h++) {
                    int rr = r + h * 8;
                    float v0 = acc[mi][ni][h * 2 + 0];
                    float v1 = acc[mi][ni][h * 2 + 1];
                    if (EPI == 1) {
                        v0 += bias[cc];
                        v1 += bias[cc + 1];
                        v0 = (v0 > 20.f) ? v0 : log1pf(__expf(v0));
                        v1 = (v1 > 20.f) ? v1 : log1pf(__expf(v1));
                    } else if (EPI == 2) {
                        v0 = fmaxf(v0, 0.f) + resid[(size_t)rr * N + cc];
                        v1 = fmaxf(v1, 0.f) + resid[(size_t)rr * N + cc + 1];
                    }
                    float2 o; o.x = v0; o.y = v1;
                    *(float2*)(C + (size_t)rr * N + cc) = o;
                }
            }
        }
    }
}

// ---------------------------------------------------------------------------
// Reduce split-K partials for x_dbl
// ---------------------------------------------------------------------------
__global__ void xdbl_reduce_kernel()
{
    int i = blockIdx.x * 256 + threadIdx.x;
    if (i < XPART) {
        float s = g_xpart[i] + g_xpart[i + XPART]
                + g_xpart[i + 2 * XPART] + g_xpart[i + 3 * XPART];
        g_xdbl[i] = s;
    }
}

// ---------------------------------------------------------------------------
// Causal depthwise conv (width 4) + bias + SiLU; input is xz[..., :DI]
// ---------------------------------------------------------------------------
__global__ void conv_silu_kernel(const float* __restrict__ Wc,
                                 const float* __restrict__ bc)
{
    int gid = blockIdx.x * blockDim.x + threadIdx.x;
    if (gid >= M_ROWS * DI_SZ) return;
    int d  = gid % DI_SZ;
    int bl = gid / DI_SZ;
    int l  = bl % L_SZ;
    float acc = bc[d];
#pragma unroll
    for (int j = 0; j < 4; j++) {
        int ll = l - 3 + j;
        if (ll >= 0)
            acc = fmaf(Wc[d * 4 + j], g_xz[(size_t)(bl - 3 + j) * DI2_SZ + d], acc);
    }
    g_xc[gid] = acc / (1.f + __expf(-acc));
}

// ---------------------------------------------------------------------------
// Selective scan + skip + gate. 16 lanes per (b,d) chain, 2 chains per warp.
// ---------------------------------------------------------------------------
__global__ __launch_bounds__(256)
void scan_kernel(const float* __restrict__ A_log,
                 const float* __restrict__ Dpar)
{
    int gtid  = blockIdx.x * 256 + threadIdx.x;
    int chain = gtid >> 4;          // 0..6143
    int n     = gtid & 15;
    int b     = chain / DI_SZ;
    int d     = chain % DI_SZ;

    float a  = -__expf(A_log[d * N_ST + n]);
    float dp = Dpar[d];
    float h  = 0.f;
    int base = b * L_SZ;

    for (int l = 0; l < L_SZ; l++) {
        int bl = base + l;
        size_t ofs = (size_t)bl * DI_SZ + d;
        float delta = g_delta[ofs];
        float u     = g_xc[ofs];
        float Bv    = g_xdbl[bl * XDBL_W + DTR_SZ + n];
        float Cv    = g_xdbl[bl * XDBL_W + DTR_SZ + N_ST + n];
        float dA    = __expf(delta * a);
        h = fmaf(dA, h, delta * Bv * u);
        float s = h * Cv;
        s += __shfl_xor_sync(0xffffffffu, s, 8);
        s += __shfl_xor_sync(0xffffffffu, s, 4);
        s += __shfl_xor_sync(0xffffffffu, s, 2);
        s += __shfl_xor_sync(0xffffffffu, s, 1);
        if (n == 0) {
            float z   = g_xz[(size_t)bl * DI2_SZ + DI_SZ + d];
            float sil = z / (1.f + __expf(-z));
            g_y[ofs]  = (s + u * dp) * sil;
        }
    }
}

// ---------------------------------------------------------------------------
extern "C" void kernel_launch(void* const* d_in, const int* in_sizes, int n_in,
                              void* d_out, int out_size)
{
    const float* input   = (const float*)d_in[0];
    const float* ln_g    = (const float*)d_in[1];
    const float* ln_b    = (const float*)d_in[2];
    const float* W_in    = (const float*)d_in[3];
    const float* W_conv  = (const float*)d_in[4];
    const float* b_conv  = (const float*)d_in[5];
    const float* W_x     = (const float*)d_in[6];
    const float* W_dt    = (const float*)d_in[7];
    const float* b_dt    = (const float*)d_in[8];
    const float* A_log   = (const float*)d_in[9];
    const float* D_param = (const float*)d_in[10];
    const float* W_out   = (const float*)d_in[11];
    float* out = (float*)d_out;

    float *xn, *xz, *xc, *xdbl, *xpart, *delta, *y;
    cudaGetSymbolAddress((void**)&xn,    g_xn);
    cudaGetSymbolAddress((void**)&xz,    g_xz);
    cudaGetSymbolAddress((void**)&xc,    g_xc);
    cudaGetSymbolAddress((void**)&xdbl,  g_xdbl);
    cudaGetSymbolAddress((void**)&xpart, g_xpart);
    cudaGetSymbolAddress((void**)&delta, g_delta);
    cudaGetSymbolAddress((void**)&y,     g_y);

    cudaFuncSetAttribute(mgemm<0>, cudaFuncAttributeMaxDynamicSharedMemorySize, GSMEM);
    cudaFuncSetAttribute(mgemm<1>, cudaFuncAttributeMaxDynamicSharedMemorySize, GSMEM);
    cudaFuncSetAttribute(mgemm<2>, cudaFuncAttributeMaxDynamicSharedMemorySize, GSMEM);

    // 1. LayerNorm
    ln_kernel<<<M_ROWS, 256>>>(input, ln_g, ln_b);

    // 2. in-proj: xz = xn @ W_in^T   (4096 x 3072 x 768)
    {
        dim3 g(DI2_SZ / 128, M_ROWS / 128, 1);
        mgemm<0><<<g, 256, GSMEM>>>(xn, D_SZ, W_in, D_SZ, xz,
                                    M_ROWS, DI2_SZ, D_SZ, nullptr, nullptr, 0);
    }

    // 3. causal depthwise conv + SiLU -> xc
    {
        int total = M_ROWS * DI_SZ;
        conv_silu_kernel<<<(total + 255) / 256, 256>>>(W_conv, b_conv);
    }

    // 4. x_dbl = xc @ W_x^T   (4096 x 80 x 1536) — split-K x4
    {
        dim3 g(1, M_ROWS / 128, KSPLIT);
        mgemm<0><<<g, 256, GSMEM>>>(xc, DI_SZ, W_x, DI_SZ, xpart,
                                    M_ROWS, XDBL_W, DI_SZ / KSPLIT,
                                    nullptr, nullptr, (size_t)XPART);
        xdbl_reduce_kernel<<<(XPART + 255) / 256, 256>>>();
    }

    // 5. delta = softplus(dt @ W_dt^T + b_dt)   (4096 x 1536 x 48)
    {
        dim3 g(DI_SZ / 128, M_ROWS / 128, 1);
        mgemm<1><<<g, 256, GSMEM>>>(xdbl, XDBL_W, W_dt, DTR_SZ, delta,
                                    M_ROWS, DI_SZ, DTR_SZ, b_dt, nullptr, 0);
    }

    // 6. selective scan + skip + gating -> y
    {
        int threads = B_SZ * DI_SZ * N_ST;   // 98304
        scan_kernel<<<threads / 256, 256>>>(A_log, D_param);
    }

    // 7. out = relu(y @ W_out^T) + input   (4096 x 768 x 1536)
    {
        dim3 g(D_SZ / 128, M_ROWS / 128, 1);
        mgemm<2><<<g, 256, GSMEM>>>(y, DI_SZ, W_out, DI_SZ, out,
                                    M_ROWS, D_SZ, DI_SZ, nullptr, input, 0);
    }
}

// round 5
// speedup vs baseline: 2.2966x; 1.8149x over previous
#include <cuda_runtime.h>
#include <cuda_bf16.h>
#include <math.h>
#include <stdint.h>

// Problem constants
#define B_SZ   4
#define L_SZ   1024
#define D_SZ   768
#define DI_SZ  1536
#define DI2_SZ 3072
#define N_ST   16
#define DTR_SZ 48
#define XDBL_W 80           // DTR + 2*N
#define M_ROWS 4096         // B*L
#define KSPLIT 4
#define XPART  (M_ROWS * XDBL_W)

// Scratch (device globals; no allocation allowed)
__device__ float g_xn  [M_ROWS * D_SZ];
__device__ float g_xz  [M_ROWS * DI2_SZ];
__device__ float g_xc  [M_ROWS * DI_SZ];
__device__ float g_xdbl[M_ROWS * XDBL_W];
__device__ float g_xpart[KSPLIT * XPART];
__device__ float g_delta[M_ROWS * DI_SZ];
__device__ float g_y   [M_ROWS * DI_SZ];

__device__ __forceinline__ void mma16(float* d,
                                      const uint32_t* a, const uint32_t* b) {
    asm volatile(
        "mma.sync.aligned.m16n8k16.row.col.f32.bf16.bf16.f32 "
        "{%0,%1,%2,%3}, {%4,%5,%6,%7}, {%8,%9}, {%0,%1,%2,%3};"
        : "+f"(d[0]), "+f"(d[1]), "+f"(d[2]), "+f"(d[3])
        : "r"(a[0]), "r"(a[1]), "r"(a[2]), "r"(a[3]), "r"(b[0]), "r"(b[1]));
}

// split a float pair into bf16x2 hi and bf16x2 lo (packed u32, low=first elem)
__device__ __forceinline__ void split2(float x, float y, uint32_t& hi, uint32_t& lo) {
    __nv_bfloat16 hx = __float2bfloat16_rn(x);
    __nv_bfloat16 hy = __float2bfloat16_rn(y);
    float rx = x - __bfloat162float(hx);
    float ry = y - __bfloat162float(hy);
    __nv_bfloat16 lx = __float2bfloat16_rn(rx);
    __nv_bfloat16 ly = __float2bfloat16_rn(ry);
    __nv_bfloat162 h2 = __halves2bfloat162(hx, hy);
    __nv_bfloat162 l2 = __halves2bfloat162(lx, ly);
    hi = *(uint32_t*)&h2;
    lo = *(uint32_t*)&l2;
}

// ---------------------------------------------------------------------------
// LayerNorm: one block (256 thr) per row of 768
// ---------------------------------------------------------------------------
__global__ void ln_kernel(const float* __restrict__ x,
                          const float* __restrict__ gam,
                          const float* __restrict__ bet)
{
    int row = blockIdx.x;
    const float* xr = x + (size_t)row * D_SZ;
    float v[3];
    float s = 0.f, sq = 0.f;
#pragma unroll
    for (int i = 0; i < 3; i++) {
        v[i] = xr[threadIdx.x + i * 256];
        s += v[i];
        sq += v[i] * v[i];
    }
#pragma unroll
    for (int o = 16; o > 0; o >>= 1) {
        s  += __shfl_xor_sync(0xffffffffu, s, o);
        sq += __shfl_xor_sync(0xffffffffu, sq, o);
    }
    __shared__ float ss[8], ssq[8];
    int w = threadIdx.x >> 5, lane = threadIdx.x & 31;
    if (lane == 0) { ss[w] = s; ssq[w] = sq; }
    __syncthreads();
    if (w == 0) {
        s  = (lane < 8) ? ss[lane]  : 0.f;
        sq = (lane < 8) ? ssq[lane] : 0.f;
#pragma unroll
        for (int o = 4; o > 0; o >>= 1) {
            s  += __shfl_xor_sync(0xffffffffu, s, o);
            sq += __shfl_xor_sync(0xffffffffu, sq, o);
        }
        if (lane == 0) { ss[0] = s; ssq[0] = sq; }
    }
    __syncthreads();
    float mu  = ss[0] * (1.f / D_SZ);
    float var = ssq[0] * (1.f / D_SZ) - mu * mu;
    float rs  = rsqrtf(var + 1e-6f);
#pragma unroll
    for (int i = 0; i < 3; i++) {
        int c = threadIdx.x + i * 256;
        g_xn[(size_t)row * D_SZ + c] = (v[i] - mu) * rs * gam[c] + bet[c];
    }
}

// ---------------------------------------------------------------------------
// Tensor-core bf16 NT GEMM (mma.sync m16n8k16), 3x-split accuracy (~2e-5).
// Pre-split hi/lo into SMEM as bf16; pass-ordered independent MMA batches.
// Tile 128x128x32, 256 threads (8 warps 2x4), warp tile 64x32.
// gridDim.z = split-K factor.
// EPI 0: plain   EPI 1: softplus(acc + bias[n])   EPI 2: relu(acc)+resid
// ---------------------------------------------------------------------------
#define SBR    20                   // u32 per smem row (32 bf16 + pad = 40 bf16)
#define TILE_U (128 * SBR)          // 2560 u32 per tile
#define GSMEM  (8 * TILE_U * 4)     // 81920 bytes

template <int EPI>
__global__ __launch_bounds__(256)
void mgemm(const float* __restrict__ A, int lda,
           const float* __restrict__ Bm, int ldb,
           float* __restrict__ C, int M, int N, int K,
           const float* __restrict__ bias,
           const float* __restrict__ resid, size_t zC)
{
    extern __shared__ uint32_t sm[];
    // tiles: Ahi[s]=s*T  Alo[s]=(2+s)*T  Bhi[s]=(4+s)*T  Blo[s]=(6+s)*T

    A += (size_t)blockIdx.z * K;       // split-K slice
    C += (size_t)blockIdx.z * zC;

    int tid = threadIdx.x;
    int wid = tid >> 5, lane = tid & 31;
    int wm = (wid & 1) * 64;
    int wn = (wid >> 1) * 32;
    int grp = lane >> 2, qd = lane & 3;
    int row0 = blockIdx.y * 128, col0 = blockIdx.x * 128;

    float acc[4][4][4];
#pragma unroll
    for (int mi = 0; mi < 4; mi++)
#pragma unroll
        for (int ni = 0; ni < 4; ni++)
#pragma unroll
            for (int e = 0; e < 4; e++) acc[mi][ni][e] = 0.f;

    int lrow = tid >> 3;            // 0..31
    int lc   = (tid & 7) * 4;       // 0,4,...,28
    int lcu  = (tid & 7) * 2;       // u32 col index

    const int nch = (K + 31) / 32;
    float4 pa[4], pb[4];

    // prefetch chunk 0
#pragma unroll
    for (int i = 0; i < 4; i++) {
        int r = lrow + 32 * i;
        bool kok = lc < K;
        pa[i] = kok ? *(const float4*)(A + (size_t)(row0 + r) * lda + lc)
                    : make_float4(0.f, 0.f, 0.f, 0.f);
        int n = col0 + r;
        pb[i] = (kok && n < N) ? *(const float4*)(Bm + (size_t)n * ldb + lc)
                               : make_float4(0.f, 0.f, 0.f, 0.f);
    }
    // split + store chunk 0 into stage 0
#pragma unroll
    for (int i = 0; i < 4; i++) {
        int r = lrow + 32 * i;
        uint32_t h0, l0, h1, l1;
        split2(pa[i].x, pa[i].y, h0, l0);
        split2(pa[i].z, pa[i].w, h1, l1);
        sm[0 * TILE_U + r * SBR + lcu]     = h0;
        sm[0 * TILE_U + r * SBR + lcu + 1] = h1;
        sm[2 * TILE_U + r * SBR + lcu]     = l0;
        sm[2 * TILE_U + r * SBR + lcu + 1] = l1;
        split2(pb[i].x, pb[i].y, h0, l0);
        split2(pb[i].z, pb[i].w, h1, l1);
        sm[4 * TILE_U + r * SBR + lcu]     = h0;
        sm[4 * TILE_U + r * SBR + lcu + 1] = h1;
        sm[6 * TILE_U + r * SBR + lcu]     = l0;
        sm[6 * TILE_U + r * SBR + lcu + 1] = l1;
    }
    __syncthreads();

    for (int c = 0; c < nch; c++) {
        int s = c & 1;
        if (c + 1 < nch) {
            int kc = (c + 1) * 32 + lc;
            bool kok = kc < K;
#pragma unroll
            for (int i = 0; i < 4; i++) {
                int r = lrow + 32 * i;
                pa[i] = kok ? *(const float4*)(A + (size_t)(row0 + r) * lda + kc)
                            : make_float4(0.f, 0.f, 0.f, 0.f);
                int n = col0 + r;
                pb[i] = (kok && n < N) ? *(const float4*)(Bm + (size_t)n * ldb + kc)
                                       : make_float4(0.f, 0.f, 0.f, 0.f);
            }
        }

        const uint32_t* shAhi = sm + s * TILE_U;
        const uint32_t* shAlo = sm + (2 + s) * TILE_U;
        const uint32_t* shBhi = sm + (4 + s) * TILE_U;
        const uint32_t* shBlo = sm + (6 + s) * TILE_U;

#pragma unroll
        for (int ks = 0; ks < 2; ks++) {
            int kb = ks * 8 + qd;     // u32 offset within row
            uint32_t ahi[4][4], bhi[4][2];
#pragma unroll
            for (int mi = 0; mi < 4; mi++) {
                int r = wm + mi * 16 + grp;
                ahi[mi][0] = shAhi[r * SBR + kb];
                ahi[mi][1] = shAhi[(r + 8) * SBR + kb];
                ahi[mi][2] = shAhi[r * SBR + kb + 4];
                ahi[mi][3] = shAhi[(r + 8) * SBR + kb + 4];
            }
#pragma unroll
            for (int ni = 0; ni < 4; ni++) {
                int n = wn + ni * 8 + grp;
                bhi[ni][0] = shBhi[n * SBR + kb];
                bhi[ni][1] = shBhi[n * SBR + kb + 4];
            }
            // pass 1: hi*hi — 16 independent MMAs
#pragma unroll
            for (int mi = 0; mi < 4; mi++)
#pragma unroll
                for (int ni = 0; ni < 4; ni++)
                    mma16(acc[mi][ni], ahi[mi], bhi[ni]);
            // pass 2: lo*hi
            {
                uint32_t alo[4][4];
#pragma unroll
                for (int mi = 0; mi < 4; mi++) {
                    int r = wm + mi * 16 + grp;
                    alo[mi][0] = shAlo[r * SBR + kb];
                    alo[mi][1] = shAlo[(r + 8) * SBR + kb];
                    alo[mi][2] = shAlo[r * SBR + kb + 4];
                    alo[mi][3] = shAlo[(r + 8) * SBR + kb + 4];
                }
#pragma unroll
                for (int mi = 0; mi < 4; mi++)
#pragma unroll
                    for (int ni = 0; ni < 4; ni++)
                        mma16(acc[mi][ni], alo[mi], bhi[ni]);
            }
            // pass 3: hi*lo
            {
                uint32_t blo[4][2];
#pragma unroll
                for (int ni = 0; ni < 4; ni++) {
                    int n = wn + ni * 8 + grp;
                    blo[ni][0] = shBlo[n * SBR + kb];
                    blo[ni][1] = shBlo[n * SBR + kb + 4];
                }
#pragma unroll
                for (int mi = 0; mi < 4; mi++)
#pragma unroll
                    for (int ni = 0; ni < 4; ni++)
                        mma16(acc[mi][ni], ahi[mi], blo[ni]);
            }
        }

        if (c + 1 < nch) {
            int s2 = (c + 1) & 1;
            __syncthreads();
#pragma unroll
            for (int i = 0; i < 4; i++) {
                int r = lrow + 32 * i;
                uint32_t h0, l0, h1, l1;
                split2(pa[i].x, pa[i].y, h0, l0);
                split2(pa[i].z, pa[i].w, h1, l1);
                sm[s2 * TILE_U + r * SBR + lcu]           = h0;
                sm[s2 * TILE_U + r * SBR + lcu + 1]       = h1;
                sm[(2 + s2) * TILE_U + r * SBR + lcu]     = l0;
                sm[(2 + s2) * TILE_U + r * SBR + lcu + 1] = l1;
                split2(pb[i].x, pb[i].y, h0, l0);
                split2(pb[i].z, pb[i].w, h1, l1);
                sm[(4 + s2) * TILE_U + r * SBR + lcu]     = h0;
                sm[(4 + s2) * TILE_U + r * SBR + lcu + 1] = h1;
                sm[(6 + s2) * TILE_U + r * SBR + lcu]     = l0;
                sm[(6 + s2) * TILE_U + r * SBR + lcu + 1] = l1;
            }
            __syncthreads();
        }
    }

    // epilogue: registers -> gmem
#pragma unroll
    for (int mi = 0; mi < 4; mi++) {
#pragma unroll
        for (int ni = 0; ni < 4; ni++) {
            int r  = row0 + wm + mi * 16 + grp;
            int cc = col0 + wn + ni * 8 + qd * 2;
            if (cc < N) {
#pragma unroll
                for (int h = 0; h < 2; h++) {
                    int rr = r + h * 8;
                    float v0 = acc[mi][ni][h * 2 + 0];
                    float v1 = acc[mi][ni][h * 2 + 1];
                    if (EPI == 1) {
                        v0 += bias[cc];
                        v1 += bias[cc + 1];
                        v0 = (v0 > 20.f) ? v0 : log1pf(__expf(v0));
                        v1 = (v1 > 20.f) ? v1 : log1pf(__expf(v1));
                    } else if (EPI == 2) {
                        v0 = fmaxf(v0, 0.f) + resid[(size_t)rr * N + cc];
                        v1 = fmaxf(v1, 0.f) + resid[(size_t)rr * N + cc + 1];
                    }
                    float2 o; o.x = v0; o.y = v1;
                    *(float2*)(C + (size_t)rr * N + cc) = o;
                }
            }
        }
    }
}

// ---------------------------------------------------------------------------
// Reduce split-K partials for x_dbl
// ---------------------------------------------------------------------------
__global__ void xdbl_reduce_kernel()
{
    int i = blockIdx.x * 256 + threadIdx.x;
    if (i < XPART) {
        float s = g_xpart[i] + g_xpart[i + XPART]
                + g_xpart[i + 2 * XPART] + g_xpart[i + 3 * XPART];
        g_xdbl[i] = s;
    }
}

// ---------------------------------------------------------------------------
// Causal depthwise conv (width 4) + bias + SiLU; 4 outputs per thread.
// ---------------------------------------------------------------------------
__global__ void conv_silu_kernel(const float* __restrict__ Wc,
                                 const float* __restrict__ bc)
{
    int gid = blockIdx.x * blockDim.x + threadIdx.x;
    if (gid >= (M_ROWS / 4) * DI_SZ) return;
    int d   = gid % DI_SZ;
    int blk = gid / DI_SZ;           // 0..1023
    int b   = blk / (L_SZ / 4);
    int l0  = (blk % (L_SZ / 4)) * 4;
    int bl0 = b * L_SZ + l0;

    float w0 = Wc[d * 4 + 0], w1 = Wc[d * 4 + 1];
    float w2 = Wc[d * 4 + 2], w3 = Wc[d * 4 + 3];
    float bb = bc[d];

    float x[7];
#pragma unroll
    for (int k = 0; k < 7; k++) {
        int l = l0 - 3 + k;
        x[k] = (l >= 0) ? g_xz[(size_t)(bl0 - 3 + k) * DI2_SZ + d] : 0.f;
    }
#pragma unroll
    for (int i = 0; i < 4; i++) {
        float acc = bb;
        acc = fmaf(w0, x[i],     acc);
        acc = fmaf(w1, x[i + 1], acc);
        acc = fmaf(w2, x[i + 2], acc);
        acc = fmaf(w3, x[i + 3], acc);
        g_xc[(size_t)(bl0 + i) * DI_SZ + d] = acc / (1.f + __expf(-acc));
    }
}

// ---------------------------------------------------------------------------
// Selective scan + skip + gate. 16 lanes per (b,d) chain, 2 chains per warp.
// Explicit register prefetch of step l+1 to break load-latency serialization.
// ---------------------------------------------------------------------------
__global__ __launch_bounds__(256)
void scan_kernel(const float* __restrict__ A_log,
                 const float* __restrict__ Dpar)
{
    int gtid  = blockIdx.x * 256 + threadIdx.x;
    int chain = gtid >> 4;          // 0..6143
    int n     = gtid & 15;
    int b     = chain / DI_SZ;
    int d     = chain % DI_SZ;

    float a  = -__expf(A_log[d * N_ST + n]);
    float dp = Dpar[d];
    float h  = 0.f;
    int base = b * L_SZ;

    const float* pd = g_delta + (size_t)base * DI_SZ + d;
    const float* pu = g_xc    + (size_t)base * DI_SZ + d;
    const float* px = g_xdbl  + (size_t)base * XDBL_W + DTR_SZ + n;
    const float* pz = g_xz    + (size_t)base * DI2_SZ + DI_SZ + d;
    float*       py = g_y     + (size_t)base * DI_SZ + d;

    float dl = pd[0], u = pu[0], Bv = px[0], Cv = px[N_ST], z = pz[0];

#pragma unroll 4
    for (int l = 0; l < L_SZ; l++) {
        float dl2 = 0.f, u2 = 0.f, Bv2 = 0.f, Cv2 = 0.f, z2 = 0.f;
        if (l + 1 < L_SZ) {
            pd += DI_SZ; pu += DI_SZ; px += XDBL_W; pz += DI2_SZ;
            dl2 = pd[0]; u2 = pu[0]; Bv2 = px[0]; Cv2 = px[N_ST]; z2 = pz[0];
        }
        float dA = __expf(dl * a);
        h = fmaf(dA, h, dl * Bv * u);
        float s = h * Cv;
        s += __shfl_xor_sync(0xffffffffu, s, 8);
        s += __shfl_xor_sync(0xffffffffu, s, 4);
        s += __shfl_xor_sync(0xffffffffu, s, 2);
        s += __shfl_xor_sync(0xffffffffu, s, 1);
        if (n == 0) {
            float sil = z / (1.f + __expf(-z));
            py[0] = (s + u * dp) * sil;
        }
        py += DI_SZ;
        dl = dl2; u = u2; Bv = Bv2; Cv = Cv2; z = z2;
    }
}

// ---------------------------------------------------------------------------
extern "C" void kernel_launch(void* const* d_in, const int* in_sizes, int n_in,
                              void* d_out, int out_size)
{
    const float* input   = (const float*)d_in[0];
    const float* ln_g    = (const float*)d_in[1];
    const float* ln_b    = (const float*)d_in[2];
    const float* W_in    = (const float*)d_in[3];
    const float* W_conv  = (const float*)d_in[4];
    const float* b_conv  = (const float*)d_in[5];
    const float* W_x     = (const float*)d_in[6];
    const float* W_dt    = (const float*)d_in[7];
    const float* b_dt    = (const float*)d_in[8];
    const float* A_log   = (const float*)d_in[9];
    const float* D_param = (const float*)d_in[10];
    const float* W_out   = (const float*)d_in[11];
    float* out = (float*)d_out;

    float *xn, *xz, *xc, *xdbl, *xpart, *delta, *y;
    cudaGetSymbolAddress((void**)&xn,    g_xn);
    cudaGetSymbolAddress((void**)&xz,    g_xz);
    cudaGetSymbolAddress((void**)&xc,    g_xc);
    cudaGetSymbolAddress((void**)&xdbl,  g_xdbl);
    cudaGetSymbolAddress((void**)&xpart, g_xpart);
    cudaGetSymbolAddress((void**)&delta, g_delta);
    cudaGetSymbolAddress((void**)&y,     g_y);

    cudaFuncSetAttribute(mgemm<0>, cudaFuncAttributeMaxDynamicSharedMemorySize, GSMEM);
    cudaFuncSetAttribute(mgemm<1>, cudaFuncAttributeMaxDynamicSharedMemorySize, GSMEM);
    cudaFuncSetAttribute(mgemm<2>, cudaFuncAttributeMaxDynamicSharedMemorySize, GSMEM);

    // 1. LayerNorm
    ln_kernel<<<M_ROWS, 256>>>(input, ln_g, ln_b);

    // 2. in-proj: xz = xn @ W_in^T   (4096 x 3072 x 768)
    {
        dim3 g(DI2_SZ / 128, M_ROWS / 128, 1);
        mgemm<0><<<g, 256, GSMEM>>>(xn, D_SZ, W_in, D_SZ, xz,
                                    M_ROWS, DI2_SZ, D_SZ, nullptr, nullptr, 0);
    }

    // 3. causal depthwise conv + SiLU -> xc
    {
        int total = (M_ROWS / 4) * DI_SZ;
        conv_silu_kernel<<<(total + 255) / 256, 256>>>(W_conv, b_conv);
    }

    // 4. x_dbl = xc @ W_x^T   (4096 x 80 x 1536) — split-K x4
    {
        dim3 g(1, M_ROWS / 128, KSPLIT);
        mgemm<0><<<g, 256, GSMEM>>>(xc, DI_SZ, W_x, DI_SZ, xpart,
                                    M_ROWS, XDBL_W, DI_SZ / KSPLIT,
                                    nullptr, nullptr, (size_t)XPART);
        xdbl_reduce_kernel<<<(XPART + 255) / 256, 256>>>();
    }

    // 5. delta = softplus(dt @ W_dt^T + b_dt)   (4096 x 1536 x 48)
    {
        dim3 g(DI_SZ / 128, M_ROWS / 128, 1);
        mgemm<1><<<g, 256, GSMEM>>>(xdbl, XDBL_W, W_dt, DTR_SZ, delta,
                                    M_ROWS, DI_SZ, DTR_SZ, b_dt, nullptr, 0);
    }

    // 6. selective scan + skip + gating -> y
    {
        int threads = B_SZ * DI_SZ * N_ST;   // 98304
        scan_kernel<<<threads / 256, 256>>>(A_log, D_param);
    }

    // 7. out = relu(y @ W_out^T) + input   (4096 x 768 x 1536)
    {
        dim3 g(D_SZ / 128, M_ROWS / 128, 1);
        mgemm<2><<<g, 256, GSMEM>>>(y, DI_SZ, W_out, DI_SZ, out,
                                    M_ROWS, D_SZ, DI_SZ, nullptr, input, 0);
    }
}